// round 16
// baseline (speedup 1.0000x reference)
#include <cuda_runtime.h>
#include <cuda_bf16.h>
#include <cstdint>

// Problem constants
#define MAX_N 50000
#define MAX_E 800000
#define F_IN  128
#define F_HID 128
#define F_OUT 64

// Scratch (device globals; no allocation allowed in kernel_launch)
__device__ float g_h1 [MAX_N * F_HID];
__device__ float g_agg[MAX_N * F_HID];
__device__ float g_h3 [MAX_N * F_OUT];
__device__ float g_dinv[MAX_N];
__device__ int   g_deg [MAX_N];
// CSR (edges sorted by dst)
__device__ int   g_rowptr[MAX_N + 1];
__device__ int   g_cursor[MAX_N];
__device__ int   g_srcs  [MAX_E];
__device__ float g_normv [MAX_E];
// Pre-split bf16 weights, [k][n] row-major (same layout as the fp32 inputs)
__device__ __nv_bfloat16 g_w1hi[128 * 128];
__device__ __nv_bfloat16 g_w1lo[128 * 128];
__device__ __nv_bfloat16 g_w2hi[128 * 64];
__device__ __nv_bfloat16 g_w2lo[128 * 64];

// ---------------------------------------------------------------------------
// helpers
// ---------------------------------------------------------------------------
__device__ __forceinline__ uint32_t smem_u32(const void* p) {
    uint32_t a;
    asm("{ .reg .u64 t; cvta.to.shared.u64 t, %1; cvt.u32.u64 %0, t; }"
        : "=r"(a) : "l"(p));
    return a;
}

__device__ __forceinline__ void split_pack(float a, float b, uint32_t& hi, uint32_t& lo) {
    __nv_bfloat16 ha = __float2bfloat16_rn(a), hb = __float2bfloat16_rn(b);
    float ra = a - __bfloat162float(ha);
    float rb = b - __bfloat162float(hb);
    __nv_bfloat16 la = __float2bfloat16_rn(ra), lb = __float2bfloat16_rn(rb);
    unsigned short uha = *(unsigned short*)&ha, uhb = *(unsigned short*)&hb;
    unsigned short ula = *(unsigned short*)&la, ulb = *(unsigned short*)&lb;
    hi = ((uint32_t)uhb << 16) | uha;
    lo = ((uint32_t)ulb << 16) | ula;
}

__device__ __forceinline__ void ldsm_x4(uint32_t* r, uint32_t addr) {
    asm volatile("ldmatrix.sync.aligned.m8n8.x4.shared.b16 {%0,%1,%2,%3}, [%4];"
                 : "=r"(r[0]), "=r"(r[1]), "=r"(r[2]), "=r"(r[3]) : "r"(addr));
}
__device__ __forceinline__ void ldsm_x4_t(uint32_t* r, uint32_t addr) {
    asm volatile("ldmatrix.sync.aligned.m8n8.x4.trans.shared.b16 {%0,%1,%2,%3}, [%4];"
                 : "=r"(r[0]), "=r"(r[1]), "=r"(r[2]), "=r"(r[3]) : "r"(addr));
}
__device__ __forceinline__ void mma_bf16(float* d, const uint32_t* a, const uint32_t* b) {
    asm volatile(
        "mma.sync.aligned.m16n8k16.row.col.f32.bf16.bf16.f32 "
        "{%0,%1,%2,%3}, {%4,%5,%6,%7}, {%8,%9}, {%0,%1,%2,%3};"
        : "+f"(d[0]), "+f"(d[1]), "+f"(d[2]), "+f"(d[3])
        : "r"(a[0]), "r"(a[1]), "r"(a[2]), "r"(a[3]), "r"(b[0]), "r"(b[1]));
}

// ---------------------------------------------------------------------------
// init: zero degrees + split weights into bf16 hi/lo (fused, one launch)
// ---------------------------------------------------------------------------
__global__ void k_init(const float* __restrict__ W1, const float* __restrict__ W2, int n) {
    int i = blockIdx.x * blockDim.x + threadIdx.x;
    if (i < n) g_deg[i] = 0;
    if (i < 128 * 128) {
        float v = W1[i];
        __nv_bfloat16 h = __float2bfloat16_rn(v);
        g_w1hi[i] = h;
        g_w1lo[i] = __float2bfloat16_rn(v - __bfloat162float(h));
    }
    if (i < 128 * 64) {
        float v = W2[i];
        __nv_bfloat16 h = __float2bfloat16_rn(v);
        g_w2hi[i] = h;
        g_w2lo[i] = __float2bfloat16_rn(v - __bfloat162float(h));
    }
}

__global__ void k_deg_count(const int* __restrict__ ei, int E) {
    int e = blockIdx.x * blockDim.x + threadIdx.x;
    if (e < E) atomicAdd(&g_deg[ei[E + e]], 1);
}

// ---------------------------------------------------------------------------
// Single-block exclusive scan over g_deg -> g_rowptr/g_cursor, dinv fused.
// 1024 threads, register prefetch of next tile, carry in registers.
// ---------------------------------------------------------------------------
__global__ void k_scan_one(int n, int E) {
    const int tid  = threadIdx.x;
    const int lane = tid & 31, wid = tid >> 5;
    __shared__ int wsum[32];
    const int ntiles = (n + 1023) >> 10;
    int carry = 0;

    int v = (tid < n) ? g_deg[tid] : 0;          // prefetch tile 0
    for (int t = 0; t < ntiles; t++) {
        int i = t * 1024 + tid;
        // prefetch next tile before the barriers
        int vnext = 0;
        if (t + 1 < ntiles) {
            int inext = i + 1024;
            vnext = (inext < n) ? g_deg[inext] : 0;
        }
        if (i < n) g_dinv[i] = rsqrtf((float)v + 1.0f);  // +1 self loop

        int x = v;
#pragma unroll
        for (int o = 1; o < 32; o <<= 1) {
            int tv = __shfl_up_sync(0xffffffffu, x, o);
            if (lane >= o) x += tv;
        }
        if (lane == 31) wsum[wid] = x;
        __syncthreads();
        if (wid == 0) {
            int y = wsum[lane];
#pragma unroll
            for (int o = 1; o < 32; o <<= 1) {
                int tv = __shfl_up_sync(0xffffffffu, y, o);
                if (lane >= o) y += tv;
            }
            wsum[lane] = y;
        }
        __syncthreads();
        int excl = x - v + (wid > 0 ? wsum[wid - 1] : 0) + carry;
        if (i < n) { g_rowptr[i] = excl; g_cursor[i] = excl; }
        carry += wsum[31];
        __syncthreads();                          // protect wsum for next tile
        v = vnext;
    }
    if (tid == 0) g_rowptr[n] = E;
}

__global__ void k_fill(const int* __restrict__ ei, int E) {
    int e = blockIdx.x * blockDim.x + threadIdx.x;
    if (e >= E) return;
    int src = ei[e];
    int dst = ei[E + e];
    int pos = atomicAdd(&g_cursor[dst], 1);
    g_srcs[pos]  = src;
    g_normv[pos] = g_dinv[src] * g_dinv[dst];
}

// ---------------------------------------------------------------------------
// CSR gather (unchanged from R10 winner)
// ---------------------------------------------------------------------------
template <int F, bool FINAL>
__global__ void k_gather(const float* __restrict__ h,
                         const float* __restrict__ bias,
                         float* __restrict__ out, int N) {
    int warp = (blockIdx.x * blockDim.x + threadIdx.x) >> 5;
    int lane = threadIdx.x & 31;
    if (warp >= N) return;
    int beg = g_rowptr[warp];
    int end = g_rowptr[warp + 1];
    float d = g_dinv[warp];
    float dd = d * d;

    if (F == 128) {
        float4 hv = *((const float4*)(h + (size_t)warp * F) + lane);
        float4 acc = make_float4(hv.x * dd, hv.y * dd, hv.z * dd, hv.w * dd);
        int e = beg;
        for (; e + 1 < end; e += 2) {
            int   s0 = __ldg(&g_srcs[e]),  s1 = __ldg(&g_srcs[e + 1]);
            float w0 = __ldg(&g_normv[e]), w1 = __ldg(&g_normv[e + 1]);
            float4 v0 = *((const float4*)(h + (size_t)s0 * F) + lane);
            float4 v1 = *((const float4*)(h + (size_t)s1 * F) + lane);
            acc.x += v0.x * w0 + v1.x * w1;
            acc.y += v0.y * w0 + v1.y * w1;
            acc.z += v0.z * w0 + v1.z * w1;
            acc.w += v0.w * w0 + v1.w * w1;
        }
        if (e < end) {
            int   s = __ldg(&g_srcs[e]);
            float w = __ldg(&g_normv[e]);
            float4 v = *((const float4*)(h + (size_t)s * F) + lane);
            acc.x += v.x * w; acc.y += v.y * w; acc.z += v.z * w; acc.w += v.w * w;
        }
        if (FINAL) {
            float4 bb = *((const float4*)bias + lane);
            acc.x = fmaxf(acc.x + bb.x, 0.0f);
            acc.y = fmaxf(acc.y + bb.y, 0.0f);
            acc.z = fmaxf(acc.z + bb.z, 0.0f);
            acc.w = fmaxf(acc.w + bb.w, 0.0f);
        }
        *((float4*)(out + (size_t)warp * F) + lane) = acc;
    } else {
        float2 hv = *((const float2*)(h + (size_t)warp * F) + lane);
        float2 acc = make_float2(hv.x * dd, hv.y * dd);
        int e = beg;
        for (; e + 1 < end; e += 2) {
            int   s0 = __ldg(&g_srcs[e]),  s1 = __ldg(&g_srcs[e + 1]);
            float w0 = __ldg(&g_normv[e]), w1 = __ldg(&g_normv[e + 1]);
            float2 v0 = *((const float2*)(h + (size_t)s0 * F) + lane);
            float2 v1 = *((const float2*)(h + (size_t)s1 * F) + lane);
            acc.x += v0.x * w0 + v1.x * w1;
            acc.y += v0.y * w0 + v1.y * w1;
        }
        if (e < end) {
            int   s = __ldg(&g_srcs[e]);
            float w = __ldg(&g_normv[e]);
            float2 v = *((const float2*)(h + (size_t)s * F) + lane);
            acc.x += v.x * w; acc.y += v.y * w;
        }
        if (FINAL) {
            float2 bb = *((const float2*)bias + lane);
            acc.x = fmaxf(acc.x + bb.x, 0.0f);
            acc.y = fmaxf(acc.y + bb.y, 0.0f);
        }
        *((float2*)(out + (size_t)warp * F) + lane) = acc;
    }
}

// ---------------------------------------------------------------------------
// Split-bf16 HMMA GEMM, K-chunked (R15 winner, unchanged)
// ---------------------------------------------------------------------------
template <int BN, bool FUSE>
__global__ void __launch_bounds__(256)
k_gemm_mma(const float* __restrict__ A,
           const __nv_bfloat16* __restrict__ Whi,
           const __nv_bfloat16* __restrict__ Wlo,
           const float* __restrict__ bias,
           float* __restrict__ H, int M) {
    constexpr int KC   = 64;
    constexpr int ASTR = KC * 2 + 16;
    constexpr int ASZ  = 128 * ASTR;
    constexpr int BSTR = BN * 2 + 16;
    constexpr int BSZ  = KC * BSTR;
    constexpr int NW   = BN / 2;
    constexpr int NF   = NW / 8;
    constexpr int NB   = NW / 16;

    extern __shared__ char smem[];
    const uint32_t sb   = smem_u32(smem);
    const uint32_t pAhi = sb;
    const uint32_t pAlo = sb + ASZ;
    const uint32_t pBhi = sb + 2 * ASZ;
    const uint32_t pBlo = sb + 2 * ASZ + BSZ;

    const int tid  = threadIdx.x;
    const int lane = tid & 31;
    const int wid  = tid >> 5;
    const int wm   = wid & 3;
    const int wn   = wid >> 2;
    const int row0 = blockIdx.x * 128;

    float d[2][NF][4];
#pragma unroll
    for (int mi = 0; mi < 2; mi++)
#pragma unroll
        for (int nf = 0; nf < NF; nf++)
#pragma unroll
            for (int c = 0; c < 4; c++) d[mi][nf][c] = 0.0f;

    const int li = lane & 7;
    const int q  = lane >> 3;
    const int r8 = (q & 1) * 8 + li;
    const int c8 = (q >> 1) * 8;

#pragma unroll
    for (int kc = 0; kc < 128; kc += KC) {
#pragma unroll
        for (int i = 0; i < 8; i++) {
            int idx  = tid + i * 256;
            int row  = idx >> 4;
            int col4 = (idx & 15) * 4;
            float4 v = make_float4(0.f, 0.f, 0.f, 0.f);
            if (row0 + row < M) {
                v = *(const float4*)(A + (size_t)(row0 + row) * 128 + kc + col4);
                if (FUSE) {
                    float4 bb = *(const float4*)(bias + kc + col4);
                    v.x = fmaxf(v.x + bb.x, 0.0f);
                    v.y = fmaxf(v.y + bb.y, 0.0f);
                    v.z = fmaxf(v.z + bb.z, 0.0f);
                    v.w = fmaxf(v.w + bb.w, 0.0f);
                }
            }
            uint32_t h01, l01, h23, l23;
            split_pack(v.x, v.y, h01, l01);
            split_pack(v.z, v.w, h23, l23);
            uint32_t off = row * ASTR + col4 * 2;
            *(uint2*)(smem + off)       = make_uint2(h01, h23);
            *(uint2*)(smem + ASZ + off) = make_uint2(l01, l23);
        }
        {
            constexpr int ROWB = BN * 2;
            constexpr int VPR  = ROWB / 16;
            for (int u = tid; u < 2 * KC * VPR; u += 256) {
                int t = u / (KC * VPR);
                int v2 = u % (KC * VPR);
                int r = v2 / VPR;
                int o = (v2 % VPR) * 16;
                const char* src = (const char*)(t ? Wlo : Whi) + (kc + r) * ROWB + o;
                char* dst = smem + (2 * ASZ + t * BSZ) + r * BSTR + o;
                *(uint4*)dst = *(const uint4*)src;
            }
        }
        __syncthreads();

#pragma unroll
        for (int term = 0; term < 3; term++) {
            uint32_t At = (term == 2) ? pAlo : pAhi;
            uint32_t Bt = (term == 1) ? pBlo : pBhi;
#pragma unroll
            for (int kb = 0; kb < KC; kb += 16) {
                uint32_t a[2][4];
#pragma unroll
                for (int mi = 0; mi < 2; mi++)
                    ldsm_x4(a[mi], At + (uint32_t)(wm * 32 + mi * 16 + r8) * ASTR
                                      + (kb + c8) * 2);
                uint32_t b[NB][4];
#pragma unroll
                for (int nb = 0; nb < NB; nb++)
                    ldsm_x4_t(b[nb], Bt + (uint32_t)(kb + r8) * BSTR
                                        + (wn * NW + nb * 16 + c8) * 2);
#pragma unroll
                for (int mi = 0; mi < 2; mi++)
#pragma unroll
                    for (int nf = 0; nf < NF; nf++)
                        mma_bf16(d[mi][nf], a[mi], &b[nf >> 1][(nf & 1) * 2]);
            }
        }
        __syncthreads();
    }

    const int g   = lane >> 2;
    const int tig = lane & 3;
#pragma unroll
    for (int mi = 0; mi < 2; mi++) {
        int r1 = row0 + wm * 32 + mi * 16 + g;
#pragma unroll
        for (int nf = 0; nf < NF; nf++) {
            int col = wn * NW + nf * 8 + tig * 2;
            if (r1 < M)
                *(float2*)(H + (size_t)r1 * BN + col) =
                    make_float2(d[mi][nf][0], d[mi][nf][1]);
            if (r1 + 8 < M)
                *(float2*)(H + (size_t)(r1 + 8) * BN + col) =
                    make_float2(d[mi][nf][2], d[mi][nf][3]);
        }
    }
}

// ---------------------------------------------------------------------------
// launch — fork/join: GEMM1 overlaps the CSR build in the captured graph
// ---------------------------------------------------------------------------
extern "C" void kernel_launch(void* const* d_in, const int* in_sizes, int n_in,
                              void* d_out, int out_size) {
    const float* x  = (const float*)d_in[0];
    const int*   ei = (const int*)  d_in[1];
    const float* W1 = (const float*)d_in[2];
    const float* b1 = (const float*)d_in[3];
    const float* W2 = (const float*)d_in[4];
    const float* b2 = (const float*)d_in[5];
    float* out = (float*)d_out;

    const int N = in_sizes[0] / F_IN;
    const int E = in_sizes[1] / 2;

    float *p_h1, *p_agg, *p_h3;
    cudaGetSymbolAddress((void**)&p_h1,  g_h1);
    cudaGetSymbolAddress((void**)&p_agg, g_agg);
    cudaGetSymbolAddress((void**)&p_h3,  g_h3);
    __nv_bfloat16 *p_w1h, *p_w1l, *p_w2h, *p_w2l;
    cudaGetSymbolAddress((void**)&p_w1h, g_w1hi);
    cudaGetSymbolAddress((void**)&p_w1l, g_w1lo);
    cudaGetSymbolAddress((void**)&p_w2h, g_w2hi);
    cudaGetSymbolAddress((void**)&p_w2l, g_w2lo);

    const int T = 256;

    const int smem1 = 2 * 18432 + 2 * 64 * (128 * 2 + 16);  // 71,680
    const int smem2 = 2 * 18432 + 2 * 64 * (64 * 2 + 16);   // 55,296
    cudaFuncSetAttribute(k_gemm_mma<128, false>,
                         cudaFuncAttributeMaxDynamicSharedMemorySize, smem1);
    cudaFuncSetAttribute(k_gemm_mma<64, true>,
                         cudaFuncAttributeMaxDynamicSharedMemorySize, smem2);

    // Fork/join resources (host-side handles only; kernel_launch runs a
    // bounded number of times — correctness + capture — so per-call creation
    // is cheap and allocation-free on the device)
    cudaStream_t s2;
    cudaEvent_t evFork, evJoin;
    cudaStreamCreateWithFlags(&s2, cudaStreamNonBlocking);
    cudaEventCreateWithFlags(&evFork, cudaEventDisableTiming);
    cudaEventCreateWithFlags(&evJoin, cudaEventDisableTiming);

    // ---- init (deg zero + weight split), then fork ----
    k_init<<<(N + T - 1) / T, T>>>(W1, W2, N);
    cudaEventRecord(evFork, 0);

    // branch A (s2): layer-1 GEMM (needs only x + split weights)
    cudaStreamWaitEvent(s2, evFork, 0);
    k_gemm_mma<128, false><<<(N + 127) / 128, 256, smem1, s2>>>(x, p_w1h, p_w1l,
                                                                nullptr, p_h1, N);
    cudaEventRecord(evJoin, s2);

    // branch B (main): CSR build
    k_deg_count<<<(E + T - 1) / T, T>>>(ei, E);
    k_scan_one <<<1, 1024>>>(N, E);
    k_fill     <<<(E + T - 1) / T, T>>>(ei, E);

    // join: gather1 needs both CSR and h1
    cudaStreamWaitEvent(0, evJoin, 0);
    k_gather<F_HID, false><<<(N + 7) / 8, 256>>>(p_h1, nullptr, p_agg, N);

    // ---- layer 2 ----
    k_gemm_mma<64, true><<<(N + 127) / 128, 256, smem2>>>(p_agg, p_w2h, p_w2l,
                                                          b1, p_h3, N);
    k_gather<F_OUT, true><<<(N + 7) / 8, 256>>>(p_h3, b2, out, N);

    // release host handles (events/streams are not needed after capture)
    cudaEventDestroy(evFork);
    cudaEventDestroy(evJoin);
    cudaStreamDestroy(s2);
}